// round 6
// baseline (speedup 1.0000x reference)
#include <cuda_runtime.h>

typedef unsigned long long ull;
typedef unsigned int u32;

#define Bv 2
#define Nv 2048
#define Fv 256
#define Hv 8
#define Ov 32
#define Lv 3
#define NBv (Nv/32)

// ---------------- scratch (device globals; no runtime allocation) ----------------
__device__ float g_h [Bv*Nv*Fv];          // current node features [B][N][F]
__device__ float g_Wh[Bv*Nv*Fv];          // projected features: heads view [B][H][N][O], out view [B][N][F]
__device__ float g_s1[Bv*Hv*Nv];
__device__ float g_s2[Bv*Hv*Nv];
__device__ u32   g_mask[Bv*Nv*NBv];       // packed adjacency bits

// ---------------- f32x2 helpers (sm_103a packed fp32) ----------------
__device__ __forceinline__ ull pack2(float lo, float hi) {
    ull r; asm("mov.b64 %0, {%1, %2};" : "=l"(r) : "f"(lo), "f"(hi)); return r;
}
__device__ __forceinline__ float2 unpack2(ull v) {
    float2 r; asm("mov.b64 {%0, %1}, %2;" : "=f"(r.x), "=f"(r.y) : "l"(v)); return r;
}
__device__ __forceinline__ void fma2(ull& d, ull a, ull b) {
    asm("fma.rn.f32x2 %0, %1, %2, %3;" : "=l"(d) : "l"(a), "l"(b), "l"(d));
}
__device__ __forceinline__ float elu1(float x) { return x > 0.f ? x : expm1f(x); }

// ---------------- init: copy x into g_h ----------------
__global__ void copy_x_kernel(const float* __restrict__ x) {
    int i = blockIdx.x * 256 + threadIdx.x;
    ((float4*)g_h)[i] = ((const float4*)x)[i];
}

// ---------------- pack adjacency into bitmask ----------------
__global__ void pack_mask_kernel(const int* __restrict__ adj) {
    int idx = blockIdx.x * 256 + threadIdx.x;         // over B*N*N
    u32 bits = __ballot_sync(0xffffffffu, adj[idx] != 0);
    if ((threadIdx.x & 31) == 0) g_mask[idx >> 5] = bits;
}

// ---------------- GEMM: Wh = h @ W  (MODE 0: heads, MODE 1: out) ----------------
template <int MODE>
__global__ void gemm_kernel(const float* __restrict__ xin,
                            const float* __restrict__ Wsrc, int l, int use_x)
{
    __shared__ __align__(16) float As[16][64];
    __shared__ __align__(16) float Bs[16][64];
    int b = blockIdx.z;
    int rowBase = blockIdx.x * 64;
    int colBase = blockIdx.y * 64;
    int t  = threadIdx.x;
    int tx = t & 15, ty = t >> 4;
    const float* hin = (use_x ? xin : g_h) + b * Nv * Fv;
    const float* Wl  = Wsrc + (MODE == 0 ? l * Hv * Fv * Ov : l * Fv * Fv);

    float acc[4][4] = {};
    for (int kt = 0; kt < Fv; kt += 16) {
        __syncthreads();
        {
            int r  = t >> 2;
            int kq = (t & 3) << 2;
            float4 av = *(const float4*)&hin[(rowBase + r) * Fv + kt + kq];
            As[kq + 0][r] = av.x; As[kq + 1][r] = av.y;
            As[kq + 2][r] = av.z; As[kq + 3][r] = av.w;
            int c   = t & 63;
            int col = colBase + c;
            #pragma unroll
            for (int q = 0; q < 4; q++) {
                int kk = (t >> 6) + q * 4;
                float v;
                if (MODE == 0) v = Wl[((col >> 5) * Fv + kt + kk) * Ov + (col & 31)];
                else           v = Wl[(kt + kk) * Fv + col];
                Bs[kk][c] = v;
            }
        }
        __syncthreads();
        #pragma unroll
        for (int kk = 0; kk < 16; kk++) {
            float4 a  = *(const float4*)&As[kk][ty * 4];
            float4 bb = *(const float4*)&Bs[kk][tx * 4];
            float ar[4] = {a.x, a.y, a.z, a.w};
            float br[4] = {bb.x, bb.y, bb.z, bb.w};
            #pragma unroll
            for (int i = 0; i < 4; i++)
                #pragma unroll
                for (int j = 0; j < 4; j++)
                    acc[i][j] += ar[i] * br[j];
        }
    }
    #pragma unroll
    for (int i = 0; i < 4; i++) {
        int n = rowBase + ty * 4 + i;
        #pragma unroll
        for (int j = 0; j < 4; j++) {
            int col = colBase + tx * 4 + j;
            if (MODE == 0) g_Wh[((b * Hv + (col >> 5)) * Nv + n) * Ov + (col & 31)] = acc[i][j];
            else           g_Wh[(b * Nv + n) * Fv + col] = acc[i][j];
        }
    }
}

// ---------------- s1/s2 = Wh . a1 / a2 (warp per row) ----------------
template <int HC, int OC>
__global__ void s_kernel(const float* __restrict__ avec, int l)
{
    int gt   = blockIdx.x * 256 + threadIdx.x;
    int row  = gt >> 5;
    int lane = gt & 31;
    if (row >= Bv * HC * Nv) return;
    int h = (row / Nv) % HC;
    const float* wr = g_Wh + row * OC;
    const float* av = avec + (l * HC + h) * 2 * OC;
    float v1 = 0.f, v2 = 0.f;
    #pragma unroll
    for (int o = lane; o < OC; o += 32) {
        float w = wr[o];
        v1 += w * av[o];
        v2 += w * av[OC + o];
    }
    #pragma unroll
    for (int off = 16; off; off >>= 1) {
        v1 += __shfl_xor_sync(0xffffffffu, v1, off);
        v2 += __shfl_xor_sync(0xffffffffu, v2, off);
    }
    if (lane == 0) { g_s1[row] = v1; g_s2[row] = v2; }
}

// ---------------- fused masked-softmax aggregation, heads stage ----------------
// grid (N/256, B*H), block 256. One thread = one query row n, full O=32 output in regs.
#define TMH 128
__global__ void attn_heads_kernel()
{
    __shared__ __align__(16) float whs[TMH][Ov];   // 16 KB
    __shared__ float s2s[TMH];
    int bh = blockIdx.y;
    int b  = bh >> 3;
    int n  = blockIdx.x * 256 + threadIdx.x;
    float s1 = g_s1[bh * Nv + n];
    const u32*   mrow = g_mask + (b * Nv + n) * NBv;
    const float* WhB  = g_Wh + bh * Nv * Ov;
    const float* s2p  = g_s2 + bh * Nv;

    ull acc2[16];
    #pragma unroll
    for (int q = 0; q < 16; q++) acc2[q] = 0ull;
    float den = 0.f;

    for (int mt = 0; mt < Nv; mt += TMH) {
        __syncthreads();
        const float4* src = (const float4*)(WhB + mt * Ov);
        float4*       dst = (float4*)whs;
        #pragma unroll
        for (int q = 0; q < 4; q++) dst[threadIdx.x + q * 256] = src[threadIdx.x + q * 256];
        if (threadIdx.x < TMH) s2s[threadIdx.x] = s2p[mt + threadIdx.x];
        __syncthreads();

        #pragma unroll
        for (int jw = 0; jw < TMH / 32; jw++) {
            u32 mbits = mrow[(mt >> 5) + jw];
            #pragma unroll 8
            for (int jj = 0; jj < 32; jj++) {
                int j = jw * 32 + jj;
                float e = s1 + s2s[j];
                e = fmaxf(e, 0.2f * e);                 // leaky relu
                float ex = __expf(e);
                float p  = ((mbits >> jj) & 1u) ? ex : 0.f;
                den += p;
                ull pp = pack2(p, p);
                const ulonglong2* wr = (const ulonglong2*)&whs[j][0];
                #pragma unroll
                for (int q = 0; q < 8; q++) {
                    ulonglong2 wv = wr[q];              // broadcast LDS.128
                    fma2(acc2[2 * q],     pp, wv.x);
                    fma2(acc2[2 * q + 1], pp, wv.y);
                }
            }
        }
    }
    float inv = 1.0f / den;
    float* orow = g_h + (b * Nv + n) * Fv + (bh & 7) * Ov;   // transpose+concat built in
    #pragma unroll
    for (int q = 0; q < 16; q++) {
        float2 v = unpack2(acc2[q]);
        v.x = elu1(v.x * inv);
        v.y = elu1(v.y * inv);
        ((float2*)orow)[q] = v;
    }
}

// ---------------- fused masked-softmax aggregation, out stage (single head, O=F) --------
// grid (N/32, B), block 256 = 8 warps; warp w owns output chunk [w*32, w*32+32),
// lanes own 32 consecutive query rows n. All smem reads are warp-broadcast.
#define TMO 32
__global__ void attn_out_kernel(float* __restrict__ dout, int final_layer)
{
    __shared__ __align__(16) float whs[TMO][Fv];   // 32 KB
    __shared__ float s2s[TMO];
    int b    = blockIdx.y;
    int w    = threadIdx.x >> 5;
    int lane = threadIdx.x & 31;
    int n    = blockIdx.x * 32 + lane;
    float s1 = g_s1[b * Nv + n];
    const u32*   mrow = g_mask + (b * Nv + n) * NBv;
    const float* WhB  = g_Wh + b * Nv * Fv;
    const float* s2p  = g_s2 + b * Nv;

    ull acc2[16];
    #pragma unroll
    for (int q = 0; q < 16; q++) acc2[q] = 0ull;
    float den = 0.f;

    for (int mt = 0; mt < Nv; mt += TMO) {
        __syncthreads();
        const float4* src = (const float4*)(WhB + mt * Fv);
        float4*       dst = (float4*)whs;
        #pragma unroll
        for (int q = 0; q < 8; q++) dst[threadIdx.x + q * 256] = src[threadIdx.x + q * 256];
        if (threadIdx.x < TMO) s2s[threadIdx.x] = s2p[mt + threadIdx.x];
        __syncthreads();

        u32 mbits = mrow[mt >> 5];                      // TMO == 32: one word per tile
        #pragma unroll 8
        for (int j = 0; j < TMO; j++) {
            float e = s1 + s2s[j];
            e = fmaxf(e, 0.2f * e);
            float ex = __expf(e);
            float p  = ((mbits >> j) & 1u) ? ex : 0.f;
            den += p;
            ull pp = pack2(p, p);
            const ulonglong2* wr = (const ulonglong2*)&whs[j][w * Ov];
            #pragma unroll
            for (int q = 0; q < 8; q++) {
                ulonglong2 wv = wr[q];                  // broadcast LDS.128
                fma2(acc2[2 * q],     pp, wv.x);
                fma2(acc2[2 * q + 1], pp, wv.y);
            }
        }
    }
    float inv = 1.0f / den;
    float* outp = final_layer ? dout : g_h;
    float* orow = outp + (b * Nv + n) * Fv + w * Ov;
    #pragma unroll
    for (int q = 0; q < 16; q++) {
        float2 v = unpack2(acc2[q]);
        v.x = elu1(elu1(v.x * inv));                    // reference applies elu twice
        v.y = elu1(elu1(v.y * inv));
        ((float2*)orow)[q] = v;
    }
}

// ---------------- launch ----------------
extern "C" void kernel_launch(void* const* d_in, const int* in_sizes, int n_in,
                              void* d_out, int out_size)
{
    const float* x       = (const float*)d_in[0];
    const int*   adj     = (const int*)d_in[1];
    const float* W_heads = (const float*)d_in[2];
    const float* a_heads = (const float*)d_in[3];
    const float* W_out   = (const float*)d_in[4];
    const float* a_out   = (const float*)d_in[5];
    float* out = (float*)d_out;

    copy_x_kernel<<<(Bv * Nv * Fv / 4) / 256, 256>>>(x);
    pack_mask_kernel<<<(Bv * Nv * Nv) / 256, 256>>>(adj);

    for (int l = 0; l < Lv; l++) {
        // heads stage
        gemm_kernel<0><<<dim3(Nv / 64, (Hv * Ov) / 64, Bv), 256>>>(x, W_heads, l, l == 0 ? 1 : 0);
        s_kernel<Hv, Ov><<<(Bv * Hv * Nv * 32) / 256, 256>>>(a_heads, l);
        attn_heads_kernel<<<dim3(Nv / 256, Bv * Hv), 256>>>();
        // out stage
        gemm_kernel<1><<<dim3(Nv / 64, Fv / 64, Bv), 256>>>(nullptr, W_out, l, 0);
        s_kernel<1, Fv><<<(Bv * Nv * 32) / 256, 256>>>(a_out, l);
        attn_out_kernel<<<dim3(Nv / 32, Bv), 256>>>(out, (l == Lv - 1) ? 1 : 0);
    }
}

// round 12
// speedup vs baseline: 1.5037x; 1.5037x over previous
#include <cuda_runtime.h>
#include <cstdint>

typedef unsigned int u32;

#define Bv 2
#define Nv 2048
#define Fv 256
#define Hv 8
#define Ov 32
#define Lv 3
#define NBv (Nv/32)

// ---------------- scratch (device globals; no runtime allocation) ----------------
__device__ float g_h  [Bv*Nv*Fv];        // current node features [B][N][F]
__device__ float g_Wh [Bv*Nv*Fv];        // projected feats fp32: heads [B][H][N][O], out [B][N][F]
__device__ float g_WhT[Bv*Fv*Nv];        // tf32-rounded transposed: heads [BH][O][N], out [B][F][N]
__device__ float g_s1[Bv*Hv*Nv];         // u1 = exp(0.2*s1)
__device__ float g_s2[Bv*Hv*Nv];         // u2 = exp(0.2*s2)
__device__ u32   g_mask[Bv*Nv*NBv];      // packed adjacency bits

__device__ __forceinline__ float elu1(float x) { return x > 0.f ? x : expm1f(x); }
__device__ __forceinline__ float tf32r(float x) {
    u32 u; asm("cvt.rna.tf32.f32 %0, %1;" : "=r"(u) : "f"(x));
    return __uint_as_float(u);
}
__device__ __forceinline__ u32 tf32b(float x) {
    u32 u; asm("cvt.rna.tf32.f32 %0, %1;" : "=r"(u) : "f"(x));
    return u;
}

// ---------------- init: copy x into g_h ----------------
__global__ void copy_x_kernel(const float* __restrict__ x) {
    int i = blockIdx.x * 256 + threadIdx.x;
    ((float4*)g_h)[i] = ((const float4*)x)[i];
}

// ---------------- pack adjacency into bitmask ----------------
__global__ void pack_mask_kernel(const int* __restrict__ adj) {
    int idx = blockIdx.x * 256 + threadIdx.x;
    u32 bits = __ballot_sync(0xffffffffu, adj[idx] != 0);
    if ((threadIdx.x & 31) == 0) g_mask[idx >> 5] = bits;
}

// ---------------- GEMM: Wh = h @ W (MODE 0: heads, MODE 1: out) ----------------
// Epilogue also writes the tf32-rounded transposed copy (mma B operand).
template <int MODE>
__global__ void gemm_kernel(const float* __restrict__ xin,
                            const float* __restrict__ Wsrc, int l, int use_x)
{
    __shared__ __align__(16) float As[16][64];
    __shared__ __align__(16) float Bs[16][64];
    int b = blockIdx.z;
    int rowBase = blockIdx.x * 64;
    int colBase = blockIdx.y * 64;
    int t  = threadIdx.x;
    int tx = t & 15, ty = t >> 4;
    const float* hin = (use_x ? xin : g_h) + b * Nv * Fv;
    const float* Wl  = Wsrc + (MODE == 0 ? l * Hv * Fv * Ov : l * Fv * Fv);

    float acc[4][4] = {};
    for (int kt = 0; kt < Fv; kt += 16) {
        __syncthreads();
        {
            int r  = t >> 2;
            int kq = (t & 3) << 2;
            float4 av = *(const float4*)&hin[(rowBase + r) * Fv + kt + kq];
            As[kq + 0][r] = av.x; As[kq + 1][r] = av.y;
            As[kq + 2][r] = av.z; As[kq + 3][r] = av.w;
            int c   = t & 63;
            int col = colBase + c;
            #pragma unroll
            for (int q = 0; q < 4; q++) {
                int kk = (t >> 6) + q * 4;
                float v;
                if (MODE == 0) v = Wl[((col >> 5) * Fv + kt + kk) * Ov + (col & 31)];
                else           v = Wl[(kt + kk) * Fv + col];
                Bs[kk][c] = v;
            }
        }
        __syncthreads();
        #pragma unroll
        for (int kk = 0; kk < 16; kk++) {
            float4 a  = *(const float4*)&As[kk][ty * 4];
            float4 bb = *(const float4*)&Bs[kk][tx * 4];
            float ar[4] = {a.x, a.y, a.z, a.w};
            float br[4] = {bb.x, bb.y, bb.z, bb.w};
            #pragma unroll
            for (int i = 0; i < 4; i++)
                #pragma unroll
                for (int j = 0; j < 4; j++)
                    acc[i][j] += ar[i] * br[j];
        }
    }
    #pragma unroll
    for (int i = 0; i < 4; i++) {
        int n = rowBase + ty * 4 + i;
        #pragma unroll
        for (int j = 0; j < 4; j++) {
            int col = colBase + tx * 4 + j;
            if (MODE == 0) g_Wh[((b * Hv + (col >> 5)) * Nv + n) * Ov + (col & 31)] = acc[i][j];
            else           g_Wh[(b * Nv + n) * Fv + col] = acc[i][j];
        }
    }
    // tf32-rounded transposed copy: rows = output feature, cols = node index
    #pragma unroll
    for (int j = 0; j < 4; j++) {
        int col  = colBase + tx * 4 + j;
        int rowT = (MODE == 0) ? ((b * Hv + (col >> 5)) * Ov + (col & 31)) : (b * Fv + col);
        float4 pk;
        pk.x = tf32r(acc[0][j]); pk.y = tf32r(acc[1][j]);
        pk.z = tf32r(acc[2][j]); pk.w = tf32r(acc[3][j]);
        *(float4*)&g_WhT[(size_t)rowT * Nv + rowBase + ty * 4] = pk;
    }
}

// ---------------- u1/u2 = exp(0.2 * (Wh . a)) (warp per row, fp32) ----------------
template <int HC, int OC>
__global__ void s_kernel(const float* __restrict__ avec, int l)
{
    int gt   = blockIdx.x * 256 + threadIdx.x;
    int row  = gt >> 5;
    int lane = gt & 31;
    if (row >= Bv * HC * Nv) return;
    int h = (row / Nv) % HC;
    const float* wr = g_Wh + (size_t)row * OC;
    const float* av = avec + (l * HC + h) * 2 * OC;
    float v1 = 0.f, v2 = 0.f;
    #pragma unroll
    for (int o = lane; o < OC; o += 32) {
        float w = wr[o];
        v1 += w * av[o];
        v2 += w * av[OC + o];
    }
    #pragma unroll
    for (int off = 16; off; off >>= 1) {
        v1 += __shfl_xor_sync(0xffffffffu, v1, off);
        v2 += __shfl_xor_sync(0xffffffffu, v2, off);
    }
    if (lane == 0) {
        g_s1[row] = __expf(0.2f * v1);    // u1
        g_s2[row] = __expf(0.2f * v2);    // u2
    }
}

// ---------------- fused masked-softmax aggregation via mma.sync tf32 ----------------
// Both modes: OC=32 output columns per CTA, 256 query rows per CTA (warp m=32 via
// two m16n8k8 A-fragments sharing every B fragment -> 1 LDS per MMA).
// MODE 0 (heads): grid (N/256, B*H).  MODE 1 (out): grid (N/256, F/32, B).
// Score trick: t = u1[n]*u2[m] = exp(0.2*(s1+s2)); exp(leaky(e)) = (t>1) ? t^5 : t.
// Numerator and denominator both use the tf32-rounded p for consistency.
template <int MODE>
__global__ void __launch_bounds__(256, 2) attn_mma_kernel(float* __restrict__ dout, int fin)
{
    constexpr int BST = 68;                          // padded smem row stride (floats)
    __shared__ __align__(16) float u2s[Nv];          // 8 KB
    __shared__ __align__(16) float Bsm[Ov * BST];    // 8.7 KB

    int t = threadIdx.x;
    int w = t >> 5, lane = t & 31;
    int gq = lane >> 2, t4 = lane & 3;

    int b, fcBase, srow;
    const float* whT;
    if (MODE == 0) {
        int bh = blockIdx.y; b = bh >> 3; fcBase = (bh & 7) * Ov;
        srow = bh * Nv;
        whT = g_WhT + (size_t)bh * Ov * Nv;
    } else {
        b = blockIdx.z; fcBase = blockIdx.y * Ov;
        srow = b * Nv;
        whT = g_WhT + ((size_t)b * Fv + fcBase) * Nv;
    }

    int warpRow = blockIdx.x * 256 + w * 32;
    int r0 = warpRow + gq;                            // rows r0 + {0,8,16,24}

    float u1v[4];
    const u32* mrow[4];
    #pragma unroll
    for (int i = 0; i < 4; i++) {
        u1v[i]  = g_s1[srow + r0 + 8 * i];
        mrow[i] = g_mask + (size_t)(b * Nv + r0 + 8 * i) * NBv;
    }

    // stage all u2 into smem (first use is after the kt-loop's leading barrier)
    #pragma unroll
    for (int q = 0; q < Nv / 1024; q++)
        ((float4*)u2s)[t + q * 256] = ((const float4*)(g_s2 + srow))[t + q * 256];

    float acc0[4][4], acc1[4][4];                     // tiles: rows gq/gq+8, gq+16/gq+24
    #pragma unroll
    for (int gi = 0; gi < 4; gi++)
        #pragma unroll
        for (int q = 0; q < 4; q++) { acc0[gi][q] = 0.f; acc1[gi][q] = 0.f; }
    float den[4] = {0.f, 0.f, 0.f, 0.f};

    for (int kt = 0; kt < Nv; kt += 64) {
        __syncthreads();
        // stage B tile: 32 rows x 64 k (fp32, already tf32-rounded), padded stride
        #pragma unroll
        for (int q = 0; q < 2; q++) {
            int idx = t + q * 256;                    // over 32*16 float4 slots
            int row = idx >> 4, seg = idx & 15;
            float4 v = *(const float4*)&whT[(size_t)row * Nv + kt + seg * 4];
            *(float4*)&Bsm[row * BST + seg * 4] = v;
        }
        __syncthreads();

        u32 mw[4] = {0, 0, 0, 0};
        #pragma unroll
        for (int c = 0; c < 8; c++) {
            int k0 = kt + c * 8;
            if ((c & 3) == 0) {
                #pragma unroll
                for (int i = 0; i < 4; i++) mw[i] = mrow[i][k0 >> 5];
            }
            int bp = (c & 3) * 8 + t4;                // bit position of k in current word

            float u2a = u2s[k0 + t4];
            float u2b = u2s[k0 + t4 + 4];

            u32 af[8];                                // [tile0: a0..a3][tile1: a0..a3]
            #pragma unroll
            for (int i = 0; i < 4; i++) {
                float ta = u1v[i] * u2a, tb = u1v[i] * u2b;
                float ta2 = ta * ta, tb2 = tb * tb;
                float pa = ta2 * ta2 * ta;  pa = ta > 1.f ? pa : ta;
                float pb = tb2 * tb2 * tb;  pb = tb > 1.f ? pb : tb;
                pa = ((mw[i] >> bp) & 1u)       ? pa : 0.f;
                pb = ((mw[i] >> (bp + 4)) & 1u) ? pb : 0.f;
                u32 ua = tf32b(pa), ub = tf32b(pb);
                den[i] += __uint_as_float(ua) + __uint_as_float(ub);
                af[(i >> 1) * 4 + (i & 1)]     = ua;  // (row, k..k+3)
                af[(i >> 1) * 4 + (i & 1) + 2] = ub;  // (row, k+4..k+7)
            }

            #pragma unroll
            for (int gi = 0; gi < 4; gi++) {
                const float* bpn = &Bsm[(gi * 8 + gq) * BST + c * 8 + t4];
                u32 b0 = __float_as_uint(bpn[0]);
                u32 b1 = __float_as_uint(bpn[4]);
                asm volatile(
                    "mma.sync.aligned.m16n8k8.row.col.f32.tf32.tf32.f32 "
                    "{%0,%1,%2,%3}, {%4,%5,%6,%7}, {%8,%9}, {%0,%1,%2,%3};"
                    : "+f"(acc0[gi][0]), "+f"(acc0[gi][1]), "+f"(acc0[gi][2]), "+f"(acc0[gi][3])
                    : "r"(af[0]), "r"(af[1]), "r"(af[2]), "r"(af[3]), "r"(b0), "r"(b1));
                asm volatile(
                    "mma.sync.aligned.m16n8k8.row.col.f32.tf32.tf32.f32 "
                    "{%0,%1,%2,%3}, {%4,%5,%6,%7}, {%8,%9}, {%0,%1,%2,%3};"
                    : "+f"(acc1[gi][0]), "+f"(acc1[gi][1]), "+f"(acc1[gi][2]), "+f"(acc1[gi][3])
                    : "r"(af[4]), "r"(af[5]), "r"(af[6]), "r"(af[7]), "r"(b0), "r"(b1));
            }
        }
    }

    // reduce den across the 4 lanes of each group (they cover all k columns)
    float inv[4];
    #pragma unroll
    for (int i = 0; i < 4; i++) {
        den[i] += __shfl_xor_sync(0xffffffffu, den[i], 1);
        den[i] += __shfl_xor_sync(0xffffffffu, den[i], 2);
        inv[i] = 1.0f / den[i];
    }

    float* outp = (MODE == 1 && fin) ? dout : g_h;
    #pragma unroll
    for (int i = 0; i < 4; i++) {
        int r = r0 + 8 * i;
        float* rowp = outp + ((size_t)(b * Nv + r)) * Fv + fcBase;
        const float (*accp)[4] = (i < 2) ? acc0 : acc1;
        int base = (i & 1) * 2;                       // 0 -> c0,c1 ; 1 -> c2,c3
        #pragma unroll
        for (int gi = 0; gi < 4; gi++) {
            float2 v;
            v.x = elu1(accp[gi][base + 0] * inv[i]);
            v.y = elu1(accp[gi][base + 1] * inv[i]);
            if (MODE == 1) { v.x = elu1(v.x); v.y = elu1(v.y); }
            *(float2*)&rowp[gi * 8 + t4 * 2] = v;
        }
    }
}

// ---------------- launch ----------------
extern "C" void kernel_launch(void* const* d_in, const int* in_sizes, int n_in,
                              void* d_out, int out_size)
{
    const float* x       = (const float*)d_in[0];
    const int*   adj     = (const int*)d_in[1];
    const float* W_heads = (const float*)d_in[2];
    const float* a_heads = (const float*)d_in[3];
    const float* W_out   = (const float*)d_in[4];
    const float* a_out   = (const float*)d_in[5];
    float* out = (float*)d_out;

    copy_x_kernel<<<(Bv * Nv * Fv / 4) / 256, 256>>>(x);
    pack_mask_kernel<<<(Bv * Nv * Nv) / 256, 256>>>(adj);

    for (int l = 0; l < Lv; l++) {
        // heads stage
        gemm_kernel<0><<<dim3(Nv / 64, (Hv * Ov) / 64, Bv), 256>>>(x, W_heads, l, l == 0 ? 1 : 0);
        s_kernel<Hv, Ov><<<(Bv * Hv * Nv * 32) / 256, 256>>>(a_heads, l);
        attn_mma_kernel<0><<<dim3(Nv / 256, Bv * Hv), 256>>>(out, 0);
        // out stage
        gemm_kernel<1><<<dim3(Nv / 64, Fv / 64, Bv), 256>>>(nullptr, W_out, l, 0);
        s_kernel<1, Fv><<<(Bv * Nv * 32) / 256, 256>>>(a_out, l);
        attn_mma_kernel<1><<<dim3(Nv / 256, Fv / Ov, Bv), 256>>>(out, (l == Lv - 1) ? 1 : 0);
    }
}

// round 13
// speedup vs baseline: 2.6707x; 1.7761x over previous
#include <cuda_runtime.h>
#include <cstdint>

typedef unsigned int u32;

#define Bv 2
#define Nv 2048
#define Fv 256
#define Hv 8
#define Ov 32
#define Lv 3
#define NBv (Nv/32)

// ---------------- scratch (device globals; no runtime allocation) ----------------
__device__ float g_h  [Bv*Nv*Fv];        // current node features [B][N][F]
__device__ float g_Wh [Bv*Nv*Fv];        // projected feats fp32: heads [B][H][N][O], out [B][N][F]
__device__ float g_WhT[Bv*Fv*Nv];        // tf32-rounded transposed: heads [BH][O][N], out [B][F][N]
__device__ float g_s1[Bv*Hv*Nv];         // u1 = exp(0.2*s1)
__device__ float g_s2[Bv*Hv*Nv];         // u2 = exp(0.2*s2)
__device__ u32   g_mask[Bv*Nv*NBv];      // packed adjacency bits

__device__ __forceinline__ float elu1(float x) { return x > 0.f ? x : expm1f(x); }
__device__ __forceinline__ float tf32r(float x) {
    u32 u; asm("cvt.rna.tf32.f32 %0, %1;" : "=r"(u) : "f"(x));
    return __uint_as_float(u);
}

// ---------------- init: copy x into g_h ----------------
__global__ void copy_x_kernel(const float* __restrict__ x) {
    int i = blockIdx.x * 256 + threadIdx.x;
    ((float4*)g_h)[i] = ((const float4*)x)[i];
}

// ---------------- pack adjacency into bitmask ----------------
__global__ void pack_mask_kernel(const int* __restrict__ adj) {
    int idx = blockIdx.x * 256 + threadIdx.x;
    u32 bits = __ballot_sync(0xffffffffu, adj[idx] != 0);
    if ((threadIdx.x & 31) == 0) g_mask[idx >> 5] = bits;
}

// ---------------- GEMM: Wh = h @ W (MODE 0: heads, MODE 1: out) ----------------
// Double-buffered smem + register prefetch one k-tile ahead (single sync/tile).
// Epilogue also writes the tf32-rounded transposed copy (mma B operand).
template <int MODE>
__global__ void gemm_kernel(const float* __restrict__ xin,
                            const float* __restrict__ Wsrc, int l, int use_x)
{
    __shared__ __align__(16) float As[2][16][64];
    __shared__ __align__(16) float Bs[2][16][64];
    int b = blockIdx.z;
    int rowBase = blockIdx.x * 64;
    int colBase = blockIdx.y * 64;
    int t  = threadIdx.x;
    int tx = t & 15, ty = t >> 4;
    const float* hin = (use_x ? xin : g_h) + b * Nv * Fv;
    const float* Wl  = Wsrc + (MODE == 0 ? l * Hv * Fv * Ov : l * Fv * Fv);

    int r  = t >> 2;
    int kq = (t & 3) << 2;
    const float* aPtr = &hin[(rowBase + r) * Fv + kq];
    int c   = t & 63;
    int col = colBase + c;
    int kb  = t >> 6;

    float4 aR = *(const float4*)(aPtr);
    float  bR[4];
    #pragma unroll
    for (int q = 0; q < 4; q++) {
        int kk = kb + q * 4;
        bR[q] = (MODE == 0) ? Wl[((col >> 5) * Fv + kk) * Ov + (col & 31)]
                            : Wl[kk * Fv + col];
    }

    float acc[4][4] = {};
    #pragma unroll 1
    for (int it = 0; it < 16; it++) {
        int buf = it & 1;
        As[buf][kq + 0][r] = aR.x; As[buf][kq + 1][r] = aR.y;
        As[buf][kq + 2][r] = aR.z; As[buf][kq + 3][r] = aR.w;
        #pragma unroll
        for (int q = 0; q < 4; q++) Bs[buf][kb + q * 4][c] = bR[q];
        __syncthreads();

        int ktn = (it < 15) ? (it + 1) * 16 : it * 16;   // clamped prefetch
        aR = *(const float4*)(aPtr + ktn);
        #pragma unroll
        for (int q = 0; q < 4; q++) {
            int kk = ktn + kb + q * 4;
            bR[q] = (MODE == 0) ? Wl[((col >> 5) * Fv + kk) * Ov + (col & 31)]
                                : Wl[kk * Fv + col];
        }

        #pragma unroll
        for (int kk = 0; kk < 16; kk++) {
            float4 a  = *(const float4*)&As[buf][kk][ty * 4];
            float4 bb = *(const float4*)&Bs[buf][kk][tx * 4];
            float ar[4] = {a.x, a.y, a.z, a.w};
            float br[4] = {bb.x, bb.y, bb.z, bb.w};
            #pragma unroll
            for (int i = 0; i < 4; i++)
                #pragma unroll
                for (int j = 0; j < 4; j++)
                    acc[i][j] += ar[i] * br[j];
        }
    }
    #pragma unroll
    for (int i = 0; i < 4; i++) {
        int n = rowBase + ty * 4 + i;
        #pragma unroll
        for (int j = 0; j < 4; j++) {
            int cl = colBase + tx * 4 + j;
            if (MODE == 0) g_Wh[((b * Hv + (cl >> 5)) * Nv + n) * Ov + (cl & 31)] = acc[i][j];
            else           g_Wh[(b * Nv + n) * Fv + cl] = acc[i][j];
        }
    }
    #pragma unroll
    for (int j = 0; j < 4; j++) {
        int cl   = colBase + tx * 4 + j;
        int rowT = (MODE == 0) ? ((b * Hv + (cl >> 5)) * Ov + (cl & 31)) : (b * Fv + cl);
        float4 pk;
        pk.x = tf32r(acc[0][j]); pk.y = tf32r(acc[1][j]);
        pk.z = tf32r(acc[2][j]); pk.w = tf32r(acc[3][j]);
        *(float4*)&g_WhT[(size_t)rowT * Nv + rowBase + ty * 4] = pk;
    }
}

// ---------------- heads u1/u2: 8 threads per row (O=32), float4 loads ----------------
__global__ void s32_kernel(const float* __restrict__ avec, int l)
{
    int gt  = blockIdx.x * 256 + threadIdx.x;
    int row = gt >> 3;
    int sub = gt & 7;
    int h = (row / Nv) % Hv;
    float4 wv = *(const float4*)&g_Wh[(size_t)row * Ov + sub * 4];
    const float* av = avec + (l * Hv + h) * 2 * Ov;
    float4 a1 = *(const float4*)&av[sub * 4];
    float4 a2 = *(const float4*)&av[Ov + sub * 4];
    float v1 = wv.x * a1.x + wv.y * a1.y + wv.z * a1.z + wv.w * a1.w;
    float v2 = wv.x * a2.x + wv.y * a2.y + wv.z * a2.z + wv.w * a2.w;
    #pragma unroll
    for (int off = 4; off; off >>= 1) {
        v1 += __shfl_xor_sync(0xffffffffu, v1, off);
        v2 += __shfl_xor_sync(0xffffffffu, v2, off);
    }
    if (sub == 0) {
        g_s1[row] = __expf(0.2f * v1);
        g_s2[row] = __expf(0.2f * v2);
    }
}

// ---------------- out-stage u1/u2 (row of 256, warp per row) ----------------
__global__ void s256_kernel(const float* __restrict__ avec, int l)
{
    int gt   = blockIdx.x * 256 + threadIdx.x;
    int row  = gt >> 5;
    int lane = gt & 31;
    const float* wr = g_Wh + (size_t)row * Fv;
    const float* av = avec + l * 2 * Fv;
    float v1 = 0.f, v2 = 0.f;
    #pragma unroll
    for (int o = lane; o < Fv; o += 32) {
        float wv = wr[o];
        v1 += wv * av[o];
        v2 += wv * av[Fv + o];
    }
    #pragma unroll
    for (int off = 16; off; off >>= 1) {
        v1 += __shfl_xor_sync(0xffffffffu, v1, off);
        v2 += __shfl_xor_sync(0xffffffffu, v2, off);
    }
    if (lane == 0) {
        g_s1[row] = __expf(0.2f * v1);
        g_s2[row] = __expf(0.2f * v2);
    }
}

// ---------------- fused masked-softmax aggregation via mma.sync tf32 ----------------
// Pipelined: mask words + B tile prefetched one kt-tile ahead; Bsm double-buffered,
// ONE __syncthreads per tile. Score: t = u1[n]*u2[m]; exp(leaky(e)) = max(t, t^5).
// Mask + tf32 truncation fused into a single AND; den uses the exact bits HMMA sees.
template <int MODE>
__global__ void __launch_bounds__(256, 2) attn_mma_kernel(float* __restrict__ dout, int fin)
{
    constexpr int BST = 68;                              // padded smem row stride (floats)
    __shared__ __align__(16) float u2s[Nv];              // 8 KB
    __shared__ __align__(16) float Bsm[2][Ov * BST];     // 17.4 KB

    int t = threadIdx.x;
    int w = t >> 5, lane = t & 31;
    int gq = lane >> 2, t4 = lane & 3;

    int b, fcBase, srow;
    const float* whT;
    if (MODE == 0) {
        int bh = blockIdx.y; b = bh >> 3; fcBase = (bh & 7) * Ov;
        srow = bh * Nv;
        whT = g_WhT + (size_t)bh * Ov * Nv;
    } else {
        b = blockIdx.z; fcBase = blockIdx.y * Ov;
        srow = b * Nv;
        whT = g_WhT + ((size_t)b * Fv + fcBase) * Nv;
    }

    int warpRow = blockIdx.x * 256 + w * 32;
    int r0 = warpRow + gq;                               // rows r0 + {0,8,16,24}

    float u1v[4];
    const u32* mrow[4];
    #pragma unroll
    for (int i = 0; i < 4; i++) {
        u1v[i]  = g_s1[srow + r0 + 8 * i];
        mrow[i] = g_mask + (size_t)(b * Nv + r0 + 8 * i) * NBv;
    }

    // stage all u2 into smem
    #pragma unroll
    for (int q = 0; q < Nv / 1024; q++)
        ((float4*)u2s)[t + q * 256] = ((const float4*)(g_s2 + srow))[t + q * 256];

    // B-tile gmem prefetch pointers (each thread: 2 float4 per tile)
    int row0 = t >> 4, seg0 = t & 15;
    int row1 = row0 + 16;
    const float* bp0 = whT + (size_t)row0 * Nv + seg0 * 4;
    const float* bp1 = whT + (size_t)row1 * Nv + seg0 * 4;

    float4 bA = *(const float4*)bp0;                     // tile 0
    float4 bB = *(const float4*)bp1;
    uint2 mq[4], mqn[4];
    #pragma unroll
    for (int i = 0; i < 4; i++) mq[i] = *(const uint2*)&mrow[i][0];

    float acc0[4][4], acc1[4][4];
    #pragma unroll
    for (int gi = 0; gi < 4; gi++)
        #pragma unroll
        for (int q = 0; q < 4; q++) { acc0[gi][q] = 0.f; acc1[gi][q] = 0.f; }
    float den[4] = {0.f, 0.f, 0.f, 0.f};

    #pragma unroll 1
    for (int tile = 0; tile < Nv / 64; tile++) {
        int kt = tile * 64;
        float* bd = Bsm[tile & 1];
        *(float4*)&bd[row0 * BST + seg0 * 4] = bA;
        *(float4*)&bd[row1 * BST + seg0 * 4] = bB;
        __syncthreads();

        int ktn = (tile < Nv / 64 - 1) ? kt + 64 : kt;   // clamped prefetch
        bA = *(const float4*)(bp0 + ktn);
        bB = *(const float4*)(bp1 + ktn);
        #pragma unroll
        for (int i = 0; i < 4; i++) mqn[i] = *(const uint2*)&mrow[i][ktn >> 5];

        #pragma unroll
        for (int c = 0; c < 8; c++) {
            int bp  = (c & 3) * 8 + t4;
            int sh1 = 31 - bp;                           // bit bp
            int sh2 = 27 - bp;                           // bit bp+4
            float u2a = u2s[kt + c * 8 + t4];
            float u2b = u2s[kt + c * 8 + t4 + 4];

            u32 af[8];
            #pragma unroll
            for (int i = 0; i < 4; i++) {
                u32 wm = (c < 4) ? mq[i].x : mq[i].y;
                u32 sma = (u32)(((int)(wm << sh1)) >> 31);
                u32 smb = (u32)(((int)(wm << sh2)) >> 31);
                float ta = u1v[i] * u2a, tb = u1v[i] * u2b;
                float ta2 = ta * ta, tb2 = tb * tb;
                float pa = fmaxf(ta, ta2 * ta2 * ta);    // exp(leaky) = max(t, t^5)
                float pb = fmaxf(tb, tb2 * tb2 * tb);
                u32 ua = __float_as_uint(pa) & sma & 0xFFFFE000u;   // mask + tf32-truncate
                u32 ub = __float_as_uint(pb) & smb & 0xFFFFE000u;
                den[i] += __uint_as_float(ua) + __uint_as_float(ub);
                af[(i >> 1) * 4 + (i & 1)]     = ua;     // (row, k..k+3)
                af[(i >> 1) * 4 + (i & 1) + 2] = ub;     // (row, k+4..k+7)
            }

            #pragma unroll
            for (int gi = 0; gi < 4; gi++) {
                const float* bpn = &bd[(gi * 8 + gq) * BST + c * 8 + t4];
                u32 b0 = __float_as_uint(bpn[0]);
                u32 b1 = __float_as_uint(bpn[4]);
                asm volatile(
                    "mma.sync.aligned.m16n8k8.row.col.f32.tf32.tf32.f32 "
                    "{%0,%1,%2,%3}, {%4,%5,%6,%7}, {%8,%9}, {%0,%1,%2,%3};"
                    : "+f"(acc0[gi][0]), "+f"(acc0[gi][1]), "+f"(acc0[gi][2]), "+f"(acc0[gi][3])
                    : "r"(af[0]), "r"(af[1]), "r"(af[2]), "r"(af[3]), "r"(b0), "r"(b1));
                asm volatile(
                    "mma.sync.aligned.m16n8k8.row.col.f32.tf32.tf32.f32 "
                    "{%0,%1,%2,%3}, {%4,%5,%6,%7}, {%8,%9}, {%0,%1,%2,%3};"
                    : "+f"(acc1[gi][0]), "+f"(acc1[gi][1]), "+f"(acc1[gi][2]), "+f"(acc1[gi][3])
                    : "r"(af[4]), "r"(af[5]), "r"(af[6]), "r"(af[7]), "r"(b0), "r"(b1));
            }
        }
        #pragma unroll
        for (int i = 0; i < 4; i++) mq[i] = mqn[i];
    }

    float inv[4];
    #pragma unroll
    for (int i = 0; i < 4; i++) {
        den[i] += __shfl_xor_sync(0xffffffffu, den[i], 1);
        den[i] += __shfl_xor_sync(0xffffffffu, den[i], 2);
        inv[i] = 1.0f / den[i];
    }

    float* outp = (MODE == 1 && fin) ? dout : g_h;
    #pragma unroll
    for (int i = 0; i < 4; i++) {
        int rr = r0 + 8 * i;
        float* rowp = outp + ((size_t)(b * Nv + rr)) * Fv + fcBase;
        const float (*accp)[4] = (i < 2) ? acc0 : acc1;
        int base = (i & 1) * 2;
        #pragma unroll
        for (int gi = 0; gi < 4; gi++) {
            float2 v;
            v.x = elu1(accp[gi][base + 0] * inv[i]);
            v.y = elu1(accp[gi][base + 1] * inv[i]);
            if (MODE == 1) { v.x = elu1(v.x); v.y = elu1(v.y); }
            *(float2*)&rowp[gi * 8 + t4 * 2] = v;
        }
    }
}

// ---------------- launch ----------------
extern "C" void kernel_launch(void* const* d_in, const int* in_sizes, int n_in,
                              void* d_out, int out_size)
{
    const float* x       = (const float*)d_in[0];
    const int*   adj     = (const int*)d_in[1];
    const float* W_heads = (const float*)d_in[2];
    const float* a_heads = (const float*)d_in[3];
    const float* W_out   = (const float*)d_in[4];
    const float* a_out   = (const float*)d_in[5];
    float* out = (float*)d_out;

    copy_x_kernel<<<(Bv * Nv * Fv / 4) / 256, 256>>>(x);
    pack_mask_kernel<<<(Bv * Nv * Nv) / 256, 256>>>(adj);

    for (int l = 0; l < Lv; l++) {
        // heads stage
        gemm_kernel<0><<<dim3(Nv / 64, (Hv * Ov) / 64, Bv), 256>>>(x, W_heads, l, l == 0 ? 1 : 0);
        s32_kernel<<<(Bv * Hv * Nv * 8) / 256, 256>>>(a_heads, l);
        attn_mma_kernel<0><<<dim3(Nv / 256, Bv * Hv), 256>>>(out, 0);
        // out stage
        gemm_kernel<1><<<dim3(Nv / 64, Fv / 64, Bv), 256>>>(nullptr, W_out, l, 0);
        s256_kernel<<<(Bv * Nv * 32) / 256, 256>>>(a_out, l);
        attn_mma_kernel<1><<<dim3(Nv / 256, Fv / Ov, Bv), 256>>>(out, (l == Lv - 1) ? 1 : 0);
    }
}

// round 14
// speedup vs baseline: 2.8914x; 1.0826x over previous
#include <cuda_runtime.h>
#include <cstdint>

typedef unsigned int u32;

#define Bv 2
#define Nv 2048
#define Fv 256
#define Hv 8
#define Ov 32
#define Lv 3
#define NBv (Nv/32)

// ---------------- scratch (device globals; no runtime allocation) ----------------
__device__ float g_h  [Bv*Nv*Fv];        // current node features [B][N][F]
__device__ float g_WhT[Bv*Fv*Nv];        // tf32-rounded transposed: heads [BH][O][N], out [B][F][N]
__device__ float g_s1p[4][Bv*Hv*Nv];     // raw s1 (heads: slot 0; out: 4 col-block partials)
__device__ float g_s2p[4][Bv*Hv*Nv];     // raw s2
__device__ u32   g_mask[Bv*Nv*NBv];      // packed adjacency bits

__device__ __forceinline__ float elu1(float x) { return x > 0.f ? x : expm1f(x); }
__device__ __forceinline__ float tf32r(float x) {
    u32 u; asm("cvt.rna.tf32.f32 %0, %1;" : "=r"(u) : "f"(x));
    return __uint_as_float(u);
}

// ---------------- pack adjacency into bitmask ----------------
__global__ void pack_mask_kernel(const int* __restrict__ adj) {
    int idx = blockIdx.x * 256 + threadIdx.x;
    u32 bits = __ballot_sync(0xffffffffu, adj[idx] != 0);
    if ((threadIdx.x & 31) == 0) g_mask[idx >> 5] = bits;
}

// ---------------- GEMM: Wh = h @ W (MODE 0: heads, MODE 1: out) ----------------
// Double-buffered smem + register prefetch. Writes ONLY the tf32 transposed copy,
// and computes s1/s2 dot products in the epilogue (s-kernels fused away).
template <int MODE>
__global__ void gemm_kernel(const float* __restrict__ xin,
                            const float* __restrict__ Wsrc,
                            const float* __restrict__ avec, int l, int use_x)
{
    __shared__ __align__(16) float As[2][16][64];
    __shared__ __align__(16) float Bs[2][16][64];
    int b = blockIdx.z;
    int by = blockIdx.y;
    int rowBase = blockIdx.x * 64;
    int colBase = by * 64;
    int t  = threadIdx.x;
    int tx = t & 15, ty = t >> 4;
    const float* hin = (use_x ? xin : g_h) + b * Nv * Fv;
    const float* Wl  = Wsrc + (MODE == 0 ? l * Hv * Fv * Ov : l * Fv * Fv);

    int r  = t >> 2;
    int kq = (t & 3) << 2;
    const float* aPtr = &hin[(rowBase + r) * Fv + kq];
    int c   = t & 63;
    int col = colBase + c;
    int kb  = t >> 6;

    float4 aR = *(const float4*)(aPtr);
    float  bR[4];
    #pragma unroll
    for (int q = 0; q < 4; q++) {
        int kk = kb + q * 4;
        bR[q] = (MODE == 0) ? Wl[((col >> 5) * Fv + kk) * Ov + (col & 31)]
                            : Wl[kk * Fv + col];
    }

    float acc[4][4] = {};
    #pragma unroll 1
    for (int it = 0; it < 16; it++) {
        int buf = it & 1;
        As[buf][kq + 0][r] = aR.x; As[buf][kq + 1][r] = aR.y;
        As[buf][kq + 2][r] = aR.z; As[buf][kq + 3][r] = aR.w;
        #pragma unroll
        for (int q = 0; q < 4; q++) Bs[buf][kb + q * 4][c] = bR[q];
        __syncthreads();

        int ktn = (it < 15) ? (it + 1) * 16 : it * 16;   // clamped prefetch
        aR = *(const float4*)(aPtr + ktn);
        #pragma unroll
        for (int q = 0; q < 4; q++) {
            int kk = ktn + kb + q * 4;
            bR[q] = (MODE == 0) ? Wl[((col >> 5) * Fv + kk) * Ov + (col & 31)]
                                : Wl[kk * Fv + col];
        }

        #pragma unroll
        for (int kk = 0; kk < 16; kk++) {
            float4 a  = *(const float4*)&As[buf][kk][ty * 4];
            float4 bb = *(const float4*)&Bs[buf][kk][tx * 4];
            float ar[4] = {a.x, a.y, a.z, a.w};
            float br[4] = {bb.x, bb.y, bb.z, bb.w};
            #pragma unroll
            for (int i = 0; i < 4; i++)
                #pragma unroll
                for (int j = 0; j < 4; j++)
                    acc[i][j] += ar[i] * br[j];
        }
    }

    // tf32-rounded transposed copy (the attention B operand)
    #pragma unroll
    for (int j = 0; j < 4; j++) {
        int cl   = colBase + tx * 4 + j;
        int rowT = (MODE == 0) ? ((b * Hv + (cl >> 5)) * Ov + (cl & 31)) : (b * Fv + cl);
        float4 pk;
        pk.x = tf32r(acc[0][j]); pk.y = tf32r(acc[1][j]);
        pk.z = tf32r(acc[2][j]); pk.w = tf32r(acc[3][j]);
        *(float4*)&g_WhT[(size_t)rowT * Nv + rowBase + ty * 4] = pk;
    }

    // fused s1/s2 epilogue
    float a1v[4], a2v[4];
    if (MODE == 0) {
        int h = 2 * by + (tx >> 3);
        const float* av = avec + (l * Hv + h) * 2 * Ov;
        #pragma unroll
        for (int j = 0; j < 4; j++) {
            a1v[j] = av[(tx & 7) * 4 + j];
            a2v[j] = av[Ov + (tx & 7) * 4 + j];
        }
    } else {
        const float* av = avec + l * 2 * Fv;
        #pragma unroll
        for (int j = 0; j < 4; j++) {
            a1v[j] = av[colBase + tx * 4 + j];
            a2v[j] = av[Fv + colBase + tx * 4 + j];
        }
    }
    #pragma unroll
    for (int i = 0; i < 4; i++) {
        float v1 = acc[i][0] * a1v[0] + acc[i][1] * a1v[1]
                 + acc[i][2] * a1v[2] + acc[i][3] * a1v[3];
        float v2 = acc[i][0] * a2v[0] + acc[i][1] * a2v[1]
                 + acc[i][2] * a2v[2] + acc[i][3] * a2v[3];
        #pragma unroll
        for (int off = 1; off <= ((MODE == 0) ? 4 : 8); off <<= 1) {
            v1 += __shfl_xor_sync(0xffffffffu, v1, off);
            v2 += __shfl_xor_sync(0xffffffffu, v2, off);
        }
        if (MODE == 0) {
            if ((tx & 7) == 0) {
                int h = 2 * by + (tx >> 3);
                int rowI = (b * Hv + h) * Nv + rowBase + ty * 4 + i;
                g_s1p[0][rowI] = v1;
                g_s2p[0][rowI] = v2;
            }
        } else {
            if (tx == 0) {
                int rowI = b * Nv + rowBase + ty * 4 + i;
                g_s1p[by][rowI] = v1;
                g_s2p[by][rowI] = v2;
            }
        }
    }
}

// ---------------- fused masked-softmax aggregation via mma.sync tf32 ----------------
// 128-thread CTAs (4 warps, warp m=32), 128 query rows per CTA -> grid 256 (one wave).
// MODE 0 (heads): grid (N/128, B*H).  MODE 1 (out): grid (N/128, F/32, B).
// Pipelined gmem (B tile + mask) one kt-tile ahead; Bsm double-buffered, 1 sync/tile.
// Score: t = u1[n]*u2[m] (u = exp(0.2*s)); exp(leaky(e)) = max(t, t^5).
// Mask + tf32 truncation fused into one AND; den uses the exact bits HMMA sees.
template <int MODE>
__global__ void __launch_bounds__(128, 4) attn_mma_kernel(float* __restrict__ dout, int fin)
{
    constexpr int BST = 68;                              // padded smem row stride (floats)
    __shared__ __align__(16) float u2s[Nv];              // 8 KB
    __shared__ __align__(16) float Bsm[2][Ov * BST];     // 17.4 KB

    int t = threadIdx.x;
    int w = t >> 5, lane = t & 31;
    int gq = lane >> 2, t4 = lane & 3;

    int b, fcBase, srow;
    const float* whT;
    if (MODE == 0) {
        int bh = blockIdx.y; b = bh >> 3; fcBase = (bh & 7) * Ov;
        srow = bh * Nv;
        whT = g_WhT + (size_t)bh * Ov * Nv;
    } else {
        b = blockIdx.z; fcBase = blockIdx.y * Ov;
        srow = b * Nv;
        whT = g_WhT + ((size_t)b * Fv + fcBase) * Nv;
    }

    int warpRow = blockIdx.x * 128 + w * 32;
    int r0 = warpRow + gq;                               // rows r0 + {0,8,16,24}

    float u1v[4];
    const u32* mrow[4];
    #pragma unroll
    for (int i = 0; i < 4; i++) {
        int rr = srow + r0 + 8 * i;
        float s = (MODE == 0) ? g_s1p[0][rr]
                : (g_s1p[0][rr] + g_s1p[1][rr] + g_s1p[2][rr] + g_s1p[3][rr]);
        u1v[i]  = __expf(0.2f * s);
        mrow[i] = g_mask + (size_t)(b * Nv + r0 + 8 * i) * NBv;
    }

    // stage all u2 = exp(0.2*s2) into smem
    #pragma unroll
    for (int q = 0; q < 4; q++) {
        int idx = (t + q * 128) * 4;
        float4 v0 = *(const float4*)&g_s2p[0][srow + idx];
        if (MODE == 1) {
            float4 v1 = *(const float4*)&g_s2p[1][srow + idx];
            float4 v2 = *(const float4*)&g_s2p[2][srow + idx];
            float4 v3 = *(const float4*)&g_s2p[3][srow + idx];
            v0.x += v1.x + v2.x + v3.x; v0.y += v1.y + v2.y + v3.y;
            v0.z += v1.z + v2.z + v3.z; v0.w += v1.w + v2.w + v3.w;
        }
        float4 o;
        o.x = __expf(0.2f * v0.x); o.y = __expf(0.2f * v0.y);
        o.z = __expf(0.2f * v0.z); o.w = __expf(0.2f * v0.w);
        *(float4*)&u2s[idx] = o;
    }

    // B-tile gmem prefetch (each thread: 4 float4 per tile, rows t>>4 + {0,8,16,24})
    int prow = t >> 4, seg0 = t & 15;
    const float* bp0 = whT + (size_t)(prow +  0) * Nv + seg0 * 4;
    const float* bp1 = whT + (size_t)(prow +  8) * Nv + seg0 * 4;
    const float* bp2 = whT + (size_t)(prow + 16) * Nv + seg0 * 4;
    const float* bp3 = whT + (size_t)(prow + 24) * Nv + seg0 * 4;

    float4 bA = *(const float4*)bp0;
    float4 bB = *(const float4*)bp1;
    float4 bC = *(const float4*)bp2;
    float4 bD = *(const float4*)bp3;
    uint2 mq[4], mqn[4];
    #pragma unroll
    for (int i = 0; i < 4; i++) mq[i] = *(const uint2*)&mrow[i][0];

    float acc0[4][4], acc1[4][4];
    #pragma unroll
    for (int gi = 0; gi < 4; gi++)
        #pragma unroll
        for (int q = 0; q < 4; q++) { acc0[gi][q] = 0.f; acc1[gi][q] = 0.f; }
    float den[4] = {0.f, 0.f, 0.f, 0.f};

    #pragma unroll 1
    for (int tile = 0; tile < Nv / 64; tile++) {
        int kt = tile * 64;
        float* bd = Bsm[tile & 1];
        *(float4*)&bd[(prow +  0) * BST + seg0 * 4] = bA;
        *(float4*)&bd[(prow +  8) * BST + seg0 * 4] = bB;
        *(float4*)&bd[(prow + 16) * BST + seg0 * 4] = bC;
        *(float4*)&bd[(prow + 24) * BST + seg0 * 4] = bD;
        __syncthreads();

        int ktn = (tile < Nv / 64 - 1) ? kt + 64 : kt;   // clamped prefetch
        bA = *(const float4*)(bp0 + ktn);
        bB = *(const float4*)(bp1 + ktn);
        bC = *(const float4*)(bp2 + ktn);
        bD = *(const float4*)(bp3 + ktn);
        #pragma unroll
        for (int i = 0; i < 4; i++) mqn[i] = *(const uint2*)&mrow[i][ktn >> 5];

        #pragma unroll
        for (int c = 0; c < 8; c++) {
            int bp  = (c & 3) * 8 + t4;
            int sh1 = 31 - bp;                           // bit bp
            int sh2 = 27 - bp;                           // bit bp+4
            float u2a = u2s[kt + c * 8 + t4];
            float u2b = u2s[kt + c * 8 + t4 + 4];

            u32 af[8];
            #pragma unroll
            for (int i = 0; i < 4; i++) {
                u32 wm = (c < 4) ? mq[i].x : mq[i].y;
                u32 sma = (u32)(((int)(wm << sh1)) >> 31);
                u32 smb = (u32)(((int)(wm << sh2)) >> 31);
                float ta = u1v[i] * u2a, tb = u1v[i] * u2b;
                float ta2 = ta * ta, tb2 = tb * tb;
                float pa = fmaxf(ta, ta2 * ta2 * ta);    // exp(leaky) = max(t, t^5)
                float pb = fmaxf(tb, tb2 * tb2 * tb);
                u32 ua = __float_as_uint(pa) & sma & 0xFFFFE000u;   // mask + tf32-truncate
                u32 ub = __float_as_uint(pb) & smb & 0xFFFFE000u;
                den[i] += __uint_as_float(ua) + __uint_as_float(ub);
                af[(i >> 1) * 4 + (i & 1)]     = ua;     // (row, k..k+3)
                af[(i >> 1) * 4 + (i & 1) + 2] = ub;     // (row, k+4..k+7)
            }

            #pragma unroll
            for (int gi = 0; gi < 4; gi++) {
                const float* bpn = &bd[(gi * 8 + gq) * BST + c * 8 + t4];
                u32 b0 = __float_as_uint(bpn[0]);
                u32 b1 = __float_as_uint(bpn[4]);
                asm volatile(
                    "mma.sync.aligned.m16n8k8.row.col.f32.tf32.tf32.f32 "
                    "{%0,%1,%2,%3}, {%4,%5,%6,%7}, {%8,%9}, {%0,%1,%2,%3};"
                    : "+f"(acc0[gi][0]), "+f"(acc0[gi][1]), "+f"(acc0[gi][2]), "+f"(acc0[gi][3])
                    : "r"(af[0]), "r"(af[1]), "r"(af[2]), "r"(af[3]), "r"(b0), "r"(b1));
                asm volatile(
                    "mma.sync.aligned.m16n8k8.row.col.f32.tf32.tf32.f32 "
                    "{%0,%1,%2,%3}, {%4,%5,%6,%7}, {%8,%9}, {%0,%1,%2,%3};"
                    : "+f"(acc1[gi][0]), "+f"(acc1[gi][1]), "+f"(acc1[gi][2]), "+f"(acc1[gi][3])
                    : "r"(af[4]), "r"(af[5]), "r"(af[6]), "r"(af[7]), "r"(b0), "r"(b1));
            }
        }
        #pragma unroll
        for (int i = 0; i < 4; i++) mq[i] = mqn[i];
    }

    float inv[4];
    #pragma unroll
    for (int i = 0; i < 4; i++) {
        den[i] += __shfl_xor_sync(0xffffffffu, den[i], 1);
        den[i] += __shfl_xor_sync(0xffffffffu, den[i], 2);
        inv[i] = 1.0f / den[i];
    }

    float* outp = (MODE == 1 && fin) ? dout : g_h;
    #pragma unroll
    for (int i = 0; i < 4; i++) {
        int rr = r0 + 8 * i;
        float* rowp = outp + ((size_t)(b * Nv + rr)) * Fv + fcBase;
        const float (*accp)[4] = (i < 2) ? acc0 : acc1;
        int base = (i & 1) * 2;
        #pragma unroll
        for (int gi = 0; gi < 4; gi++) {
            float2 v;
            v.x = elu1(accp[gi][base + 0] * inv[i]);
            v.y = elu1(accp[gi][base + 1] * inv[i]);
            if (MODE == 1) { v.x = elu1(v.x); v.y = elu1(v.y); }
            *(float2*)&rowp[gi * 8 + t4 * 2] = v;
        }
    }
}

// ---------------- launch ----------------
extern "C" void kernel_launch(void* const* d_in, const int* in_sizes, int n_in,
                              void* d_out, int out_size)
{
    const float* x       = (const float*)d_in[0];
    const int*   adj     = (const int*)d_in[1];
    const float* W_heads = (const float*)d_in[2];
    const float* a_heads = (const float*)d_in[3];
    const float* W_out   = (const float*)d_in[4];
    const float* a_out   = (const float*)d_in[5];
    float* out = (float*)d_out;

    pack_mask_kernel<<<(Bv * Nv * Nv) / 256, 256>>>(adj);

    for (int l = 0; l < Lv; l++) {
        // heads stage
        gemm_kernel<0><<<dim3(Nv / 64, (Hv * Ov) / 64, Bv), 256>>>(x, W_heads, a_heads, l, l == 0 ? 1 : 0);
        attn_mma_kernel<0><<<dim3(Nv / 128, Bv * Hv), 128>>>(out, 0);
        // out stage
        gemm_kernel<1><<<dim3(Nv / 64, Fv / 64, Bv), 256>>>(nullptr, W_out, a_out, l, 0);
        attn_mma_kernel<1><<<dim3(Nv / 128, Fv / Ov, Bv), 128>>>(out, (l == Lv - 1) ? 1 : 0);
    }
}